// round 3
// baseline (speedup 1.0000x reference)
#include <cuda_runtime.h>
#include <cstdint>

#define H_FEAT 512
#define W_FEAT 512
#define K_ANCH 9
#define N_ANCH (H_FEAT * W_FEAT * K_ANCH)   // 2359296
#define TOP_K 4000
#define IMG_DIM 16384.0f
#define NMS_IOU_T 0.3f
#define N_BINS (1 << 20)
#define BIN_SHIFT 12
#define CAP 4096
#define COL_BLOCKS 63
#define ROW_WORDS 64                         // padded row stride (512B)
#define MASK_ROWS 4096
#define N_GROUPS 63

// ---------------- static device scratch (no allocation allowed) ----------------
__device__ unsigned int        g_hist[N_BINS];            // 4 MB
__device__ unsigned int        g_bsum[1024];
__device__ unsigned int        g_count;
__device__ unsigned int        g_cutlow;
__device__ unsigned long long  g_keys[CAP];
__device__ float               g_x1[TOP_K], g_y1[TOP_K], g_x2[TOP_K], g_y2[TOP_K], g_area[TOP_K];
// Zero-initialized at load. Lower-triangle/padding words NEVER written -> stay 0.
__device__ unsigned long long  g_mask[(size_t)MASK_ROWS * ROW_WORDS];   // 2 MB
__device__ __align__(16) unsigned long long g_diag[4096];               // 63*64 used

// ---------------- helpers (forbid FMA contraction / fast-math drift) ----------
__device__ __forceinline__ float softmax_p1(float l0, float l1, float& p0) {
    float m  = fmaxf(l0, l1);
    float e0 = expf(__fsub_rn(l0, m));
    float e1 = expf(__fsub_rn(l1, m));
    float s  = __fadd_rn(e0, e1);
    p0 = __fdiv_rn(e0, s);
    return __fdiv_rn(e1, s);
}

// ---------------- K0: reset ----------------------------------------------------
__global__ void zero_kernel() {
    int i = blockIdx.x * blockDim.x + threadIdx.x;
    if (i < N_BINS) g_hist[i] = 0u;
    if (i == 0) g_count = 0u;
}

// ---------------- K1: histogram of d = l1 - l0 bits (no exp/div) ---------------
__global__ void hist_kernel(const float* __restrict__ obj) {
    int i = blockIdx.x * blockDim.x + threadIdx.x;
    if (i >= N_ANCH) return;
    float2 v = reinterpret_cast<const float2*>(obj)[i];   // elem offset 2*i
    float d = __fsub_rn(v.y, v.x);
    if (d > 0.0f) {
        unsigned bin = __float_as_uint(d) >> BIN_SHIFT;
        atomicAdd(&g_hist[bin], 1u);
    }
}

// ---------------- K2a: coarse per-1024-bin sums --------------------------------
__global__ void bsum_kernel() {
    __shared__ unsigned s[1024];
    int t = threadIdx.x;
    s[t] = g_hist[blockIdx.x * 1024 + t];
    __syncthreads();
    for (int off = 512; off > 0; off >>= 1) {
        if (t < off) s[t] += s[t + off];
        __syncthreads();
    }
    if (t == 0) g_bsum[blockIdx.x] = s[0];
}

// ---------------- K2b: two-level suffix scan -> g_cutlow -----------------------
__global__ void cut_kernel() {
    __shared__ unsigned suf[1024];
    __shared__ int s_cb;
    __shared__ unsigned s_above;
    int t = threadIdx.x;
    if (t == 0) s_cb = -1;
    suf[t] = g_bsum[t];
    __syncthreads();
    for (int off = 1; off < 1024; off <<= 1) {
        unsigned v = (t + off < 1024) ? suf[t + off] : 0u;
        __syncthreads();
        suf[t] += v;
        __syncthreads();
    }
    if (suf[t] >= (unsigned)TOP_K && (t == 1023 || suf[t + 1] < (unsigned)TOP_K)) {
        s_cb = t;
        s_above = (t == 1023) ? 0u : suf[t + 1];
    }
    __syncthreads();
    int cb = s_cb;
    if (cb < 0) { if (t == 0) g_cutlow = 0u; return; }
    unsigned above = s_above;
    __syncthreads();
    suf[t] = g_hist[cb * 1024 + t];
    __syncthreads();
    for (int off = 1; off < 1024; off <<= 1) {
        unsigned v = (t + off < 1024) ? suf[t + off] : 0u;
        __syncthreads();
        suf[t] += v;
        __syncthreads();
    }
    if (suf[t] + above >= (unsigned)TOP_K &&
        (t == 1023 || suf[t + 1] + above < (unsigned)TOP_K)) {
        int cutbin = cb * 1024 + t;
        g_cutlow = (cutbin > 0) ? (unsigned)(cutbin - 1) : 0u;  // -1 bin safety slack
    }
}

// ---------------- K3: collect candidates, exact p1 keys ------------------------
__global__ void collect_kernel(const float* __restrict__ obj) {
    int i = blockIdx.x * blockDim.x + threadIdx.x;
    if (i >= N_ANCH) return;
    float2 v = reinterpret_cast<const float2*>(obj)[i];
    float d = __fsub_rn(v.y, v.x);
    if (d > 0.0f) {
        unsigned bin = __float_as_uint(d) >> BIN_SHIFT;
        if (bin >= g_cutlow) {
            // exact p1, bit-identical to full softmax for d > 0 (e1 = expf(0) = 1)
            float e0 = expf(__fsub_rn(v.x, v.y));
            float s  = __fadd_rn(e0, 1.0f);
            float p1 = __fdiv_rn(1.0f, s);
            unsigned pos = atomicAdd(&g_count, 1u);
            if (pos < CAP) {
                g_keys[pos] = ((unsigned long long)__float_as_uint(p1) << 32) |
                              (unsigned long long)(0xFFFFFFFFu - (unsigned)i);
            }
        }
    }
}

// ---------------- K4: one-block bitonic sort (descending), n = 4096 ------------
__global__ void sort_kernel() {
    __shared__ unsigned long long s[CAP];
    unsigned cnt = g_count;
    if (cnt > CAP) cnt = CAP;
    for (int i = threadIdx.x; i < CAP; i += blockDim.x)
        s[i] = (i < (int)cnt) ? g_keys[i] : 0ULL;
    __syncthreads();
    for (int k = 2; k <= CAP; k <<= 1) {
        for (int j = k >> 1; j > 0; j >>= 1) {
            for (int i = threadIdx.x; i < CAP; i += blockDim.x) {
                int ixj = i ^ j;
                if (ixj > i) {
                    unsigned long long a = s[i], b = s[ixj];
                    bool up = ((i & k) == 0);
                    if (up ? (a < b) : (a > b)) { s[i] = b; s[ixj] = a; }
                }
            }
            __syncthreads();
        }
    }
    for (int i = threadIdx.x; i < CAP; i += blockDim.x) g_keys[i] = s[i];
}

// ---------------- K5: decode boxes, write b & o, prep NMS inputs ---------------
__global__ void finalize_kernel(const float* __restrict__ obj,
                                const float* __restrict__ reg,
                                const float* __restrict__ anc,
                                float* __restrict__ out) {
    int t = blockIdx.x * blockDim.x + threadIdx.x;
    if (t >= TOP_K) return;
    unsigned long long key = g_keys[t];
    if (key == 0ULL) {
        out[t * 4 + 0] = 0.f; out[t * 4 + 1] = 0.f; out[t * 4 + 2] = 0.f; out[t * 4 + 3] = 0.f;
        out[TOP_K * 4 + t * 2 + 0] = 0.f; out[TOP_K * 4 + t * 2 + 1] = 0.f;
        g_x1[t] = 0.f; g_y1[t] = 0.f; g_x2[t] = 0.f; g_y2[t] = 0.f; g_area[t] = 0.f;
        return;
    }
    unsigned idx = 0xFFFFFFFFu - (unsigned)(key & 0xFFFFFFFFull);

    const float* po = obj + (size_t)idx * 2;
    float p0;
    float p1 = softmax_p1(po[0], po[1], p0);

    const float* pr = reg + (size_t)idx * 4;
    float r0 = pr[0], r1 = pr[1], r2 = pr[2], r3 = pr[3];
    const float* pa = anc + (size_t)idx * 4;
    float a0 = pa[0], a1 = pa[1], a2 = pa[2], a3 = pa[3];

    float cx = __fadd_rn(__fadd_rn(a0, __fmul_rn(a2, 0.5f)), __fmul_rn(r0, a2));
    float cy = __fadd_rn(__fadd_rn(a1, __fmul_rn(a3, 0.5f)), __fmul_rn(r1, a3));
    float w  = __fmul_rn(a2, expf(r2));
    float h  = __fmul_rn(a3, expf(r3));
    float x1u = __fsub_rn(cx, __fmul_rn(w, 0.5f));
    float y1u = __fsub_rn(cy, __fmul_rn(h, 0.5f));

    float x1 = fminf(fmaxf(x1u, 0.0f), IMG_DIM);
    float y1 = fminf(fmaxf(y1u, 0.0f), IMG_DIM);
    float x2 = fminf(fmaxf(__fadd_rn(x1u, w), 0.0f), IMG_DIM);
    float y2 = fminf(fmaxf(__fadd_rn(y1u, h), 0.0f), IMG_DIM);
    float bw = __fsub_rn(x2, x1);
    float bh = __fsub_rn(y2, y1);

    out[t * 4 + 0] = x1;
    out[t * 4 + 1] = y1;
    out[t * 4 + 2] = bw;
    out[t * 4 + 3] = bh;
    out[TOP_K * 4 + t * 2 + 0] = p0;
    out[TOP_K * 4 + t * 2 + 1] = p1;

    g_x1[t] = x1;
    g_y1[t] = y1;
    g_x2[t] = __fadd_rn(x1, bw);
    g_y2[t] = __fadd_rn(y1, bh);
    g_area[t] = __fmul_rn(bw, bh);
}

// ---------------- K6: NMS bitmask (upper triangle) + compact diagonal ----------
__global__ void mask_kernel() {
    int cb = blockIdx.x, rb = blockIdx.y;
    if (cb < rb) return;
    int tid = threadIdx.x;
    __shared__ float sx1[64], sy1[64], sx2[64], sy2[64], sa[64];
    int j0 = cb * 64 + tid;
    if (j0 < TOP_K) {
        sx1[tid] = g_x1[j0]; sy1[tid] = g_y1[j0];
        sx2[tid] = g_x2[j0]; sy2[tid] = g_y2[j0];
        sa[tid]  = g_area[j0];
    }
    __syncthreads();
    int i = rb * 64 + tid;
    if (i >= TOP_K) return;
    float x1i = g_x1[i], y1i = g_y1[i], x2i = g_x2[i], y2i = g_y2[i], ai = g_area[i];
    unsigned long long bits = 0ULL;
    int jmax = min(64, TOP_K - cb * 64);
    for (int jj = 0; jj < jmax; jj++) {
        int j = cb * 64 + jj;
        if (j > i) {
            float xx1 = fmaxf(x1i, sx1[jj]);
            float yy1 = fmaxf(y1i, sy1[jj]);
            float xx2 = fminf(x2i, sx2[jj]);
            float yy2 = fminf(y2i, sy2[jj]);
            float iw = fmaxf(__fsub_rn(xx2, xx1), 0.0f);
            float ih = fmaxf(__fsub_rn(yy2, yy1), 0.0f);
            float inter = __fmul_rn(iw, ih);
            float denom = __fadd_rn(__fsub_rn(__fadd_rn(ai, sa[jj]), inter), 1e-8f);
            float iou = __fdiv_rn(inter, denom);
            if (iou > NMS_IOU_T) bits |= (1ULL << jj);
        }
    }
    g_mask[(size_t)i * ROW_WORDS + cb] = bits;
    if (rb == cb) g_diag[cb * 64 + tid] = bits;     // coalesced copy for reduce
}

// ---------------- K7: blocked greedy reduce, single warp -----------------------
__global__ void __launch_bounds__(32) nms_reduce_kernel(float* __restrict__ keep_out) {
    const int lane = threadIdx.x;
    unsigned long long acc0 = 0ULL, acc1 = 0ULL;
    unsigned long long diag[64];

    if (lane == 0) {
        const ulonglong2* dp = reinterpret_cast<const ulonglong2*>(g_diag);
        #pragma unroll
        for (int q = 0; q < 32; q++) { ulonglong2 v = dp[q]; diag[2*q] = v.x; diag[2*q+1] = v.y; }
    }

    for (int g = 0; g < N_GROUPS; g++) {
        const int r0 = g * 64;

        unsigned long long wsel = (g & 1) ? acc1 : acc0;
        unsigned long long word = __shfl_sync(0xffffffffu, wsel, g >> 1);

        unsigned long long keepm = 0ULL;
        if (lane == 0) {
            #pragma unroll
            for (int jj = 0; jj < 64; jj++) {
                unsigned long long bit = (word >> jj) & 1ULL;   // 1 = removed
                unsigned long long m = bit - 1ULL;              // keep -> all ones
                word |= diag[jj] & m;
                keepm |= (bit ^ 1ULL) << jj;
            }
        }
        keepm = __shfl_sync(0xffffffffu, keepm, 0);

        int r = r0 + 2 * lane;
        if (r < TOP_K)     keep_out[r]     = (float)((keepm >> (2 * lane)) & 1ULL);
        if (r + 1 < TOP_K) keep_out[r + 1] = (float)((keepm >> (2 * lane + 1)) & 1ULL);

        if (lane == 0 && g + 1 < N_GROUPS) {
            const ulonglong2* dp = reinterpret_cast<const ulonglong2*>(g_diag + (size_t)(g + 1) * 64);
            #pragma unroll
            for (int q = 0; q < 32; q++) { ulonglong2 v = dp[q]; diag[2*q] = v.x; diag[2*q+1] = v.y; }
        }

        // Boundary: OR only KEPT rows' mask words into distributed acc.
        const unsigned long long* base = g_mask + (size_t)r0 * ROW_WORDS + 2 * lane;
        unsigned long long kk = keepm;
        while (kk) {
            int jj = __ffsll((long long)kk) - 1;
            kk &= kk - 1ULL;
            ulonglong2 v = *reinterpret_cast<const ulonglong2*>(base + (size_t)jj * ROW_WORDS);
            acc0 |= v.x;
            acc1 |= v.y;
        }
    }
}

// ---------------- launch -------------------------------------------------------
extern "C" void kernel_launch(void* const* d_in, const int* in_sizes, int n_in,
                              void* d_out, int out_size) {
    const float* obj = (const float*)d_in[0];
    const float* reg = (const float*)d_in[1];
    const float* anc = (const float*)d_in[2];
    float* out = (float*)d_out;

    zero_kernel<<<N_BINS / 256, 256>>>();
    hist_kernel<<<(N_ANCH + 255) / 256, 256>>>(obj);
    bsum_kernel<<<1024, 1024>>>();
    cut_kernel<<<1, 1024>>>();
    collect_kernel<<<(N_ANCH + 255) / 256, 256>>>(obj);
    sort_kernel<<<1, 1024>>>();
    finalize_kernel<<<(TOP_K + 255) / 256, 256>>>(obj, reg, anc, out);
    mask_kernel<<<dim3(COL_BLOCKS, COL_BLOCKS), 64>>>();
    nms_reduce_kernel<<<1, 32>>>(out + TOP_K * 4 + TOP_K * 2);
}

// round 4
// speedup vs baseline: 3.2336x; 3.2336x over previous
#include <cuda_runtime.h>
#include <cstdint>

#define H_FEAT 512
#define W_FEAT 512
#define K_ANCH 9
#define N_ANCH (H_FEAT * W_FEAT * K_ANCH)   // 2359296
#define TOP_K 4000
#define IMG_DIM 16384.0f
#define NMS_IOU_T 0.3f
#define N_BINS (1 << 20)
#define BIN_SHIFT 12
#define CAP 4096
#define COL_BLOCKS 63
#define ROW_WORDS 64                         // padded row stride (512B)
#define MASK_ROWS 4096
#define N_GROUPS 63

// ---------------- static device scratch (no allocation allowed) ----------------
__device__ unsigned int        g_hist[N_BINS];            // 4 MB
__device__ unsigned int        g_bsum[1024];
__device__ unsigned int        g_count;
__device__ unsigned int        g_cutlow;
__device__ unsigned long long  g_keys[CAP];
__device__ float               g_x1[TOP_K], g_y1[TOP_K], g_x2[TOP_K], g_y2[TOP_K], g_area[TOP_K];
// Zero-initialized at load. Lower-triangle/padding words NEVER written -> stay 0.
__device__ unsigned long long  g_mask[(size_t)MASK_ROWS * ROW_WORDS];   // 2 MB
__device__ __align__(16) unsigned long long g_diag[4096];               // 63*64 used

// ---------------- helpers (forbid FMA contraction / fast-math drift) ----------
__device__ __forceinline__ float softmax_p1(float l0, float l1, float& p0) {
    float m  = fmaxf(l0, l1);
    float e0 = expf(__fsub_rn(l0, m));
    float e1 = expf(__fsub_rn(l1, m));
    float s  = __fadd_rn(e0, e1);
    p0 = __fdiv_rn(e0, s);
    return __fdiv_rn(e1, s);
}

// ---------------- K0: reset ----------------------------------------------------
__global__ void zero_kernel() {
    int i = blockIdx.x * blockDim.x + threadIdx.x;
    if (i < N_BINS) g_hist[i] = 0u;
    if (i == 0) g_count = 0u;
}

// ---------------- K1: histogram of d = l1 - l0 bits (no exp/div) ---------------
__global__ void hist_kernel(const float* __restrict__ obj) {
    int i = blockIdx.x * blockDim.x + threadIdx.x;
    if (i >= N_ANCH) return;
    float2 v = reinterpret_cast<const float2*>(obj)[i];   // elem offset 2*i
    float d = __fsub_rn(v.y, v.x);
    if (d > 0.0f) {
        unsigned bin = __float_as_uint(d) >> BIN_SHIFT;
        atomicAdd(&g_hist[bin], 1u);
    }
}

// ---------------- K2a: coarse per-1024-bin sums --------------------------------
__global__ void bsum_kernel() {
    __shared__ unsigned s[1024];
    int t = threadIdx.x;
    s[t] = g_hist[blockIdx.x * 1024 + t];
    __syncthreads();
    for (int off = 512; off > 0; off >>= 1) {
        if (t < off) s[t] += s[t + off];
        __syncthreads();
    }
    if (t == 0) g_bsum[blockIdx.x] = s[0];
}

// ---------------- K2b: two-level suffix scan -> g_cutlow -----------------------
__global__ void cut_kernel() {
    __shared__ unsigned suf[1024];
    __shared__ int s_cb;
    __shared__ unsigned s_above;
    int t = threadIdx.x;
    if (t == 0) s_cb = -1;
    suf[t] = g_bsum[t];
    __syncthreads();
    for (int off = 1; off < 1024; off <<= 1) {
        unsigned v = (t + off < 1024) ? suf[t + off] : 0u;
        __syncthreads();
        suf[t] += v;
        __syncthreads();
    }
    if (suf[t] >= (unsigned)TOP_K && (t == 1023 || suf[t + 1] < (unsigned)TOP_K)) {
        s_cb = t;
        s_above = (t == 1023) ? 0u : suf[t + 1];
    }
    __syncthreads();
    int cb = s_cb;
    if (cb < 0) { if (t == 0) g_cutlow = 0u; return; }
    unsigned above = s_above;
    __syncthreads();
    suf[t] = g_hist[cb * 1024 + t];
    __syncthreads();
    for (int off = 1; off < 1024; off <<= 1) {
        unsigned v = (t + off < 1024) ? suf[t + off] : 0u;
        __syncthreads();
        suf[t] += v;
        __syncthreads();
    }
    if (suf[t] + above >= (unsigned)TOP_K &&
        (t == 1023 || suf[t + 1] + above < (unsigned)TOP_K)) {
        int cutbin = cb * 1024 + t;
        g_cutlow = (cutbin > 0) ? (unsigned)(cutbin - 1) : 0u;  // -1 bin safety slack
    }
}

// ---------------- K3: collect candidates, exact p1 keys ------------------------
__global__ void collect_kernel(const float* __restrict__ obj) {
    int i = blockIdx.x * blockDim.x + threadIdx.x;
    if (i >= N_ANCH) return;
    float2 v = reinterpret_cast<const float2*>(obj)[i];
    float d = __fsub_rn(v.y, v.x);
    if (d > 0.0f) {
        unsigned bin = __float_as_uint(d) >> BIN_SHIFT;
        if (bin >= g_cutlow) {
            // exact p1, bit-identical to full softmax for d > 0 (e1 = expf(0) = 1)
            float e0 = expf(__fsub_rn(v.x, v.y));
            float s  = __fadd_rn(e0, 1.0f);
            float p1 = __fdiv_rn(1.0f, s);
            unsigned pos = atomicAdd(&g_count, 1u);
            if (pos < CAP) {
                g_keys[pos] = ((unsigned long long)__float_as_uint(p1) << 32) |
                              (unsigned long long)(0xFFFFFFFFu - (unsigned)i);
            }
        }
    }
}

// ---------------- K4: one-block bitonic sort (descending), n = 4096 ------------
__global__ void sort_kernel() {
    __shared__ unsigned long long s[CAP];
    unsigned cnt = g_count;
    if (cnt > CAP) cnt = CAP;
    for (int i = threadIdx.x; i < CAP; i += blockDim.x)
        s[i] = (i < (int)cnt) ? g_keys[i] : 0ULL;
    __syncthreads();
    for (int k = 2; k <= CAP; k <<= 1) {
        for (int j = k >> 1; j > 0; j >>= 1) {
            for (int i = threadIdx.x; i < CAP; i += blockDim.x) {
                int ixj = i ^ j;
                if (ixj > i) {
                    unsigned long long a = s[i], b = s[ixj];
                    bool up = ((i & k) == 0);
                    if (up ? (a < b) : (a > b)) { s[i] = b; s[ixj] = a; }
                }
            }
            __syncthreads();
        }
    }
    for (int i = threadIdx.x; i < CAP; i += blockDim.x) g_keys[i] = s[i];
}

// ---------------- K5: decode boxes, write b & o, prep NMS inputs ---------------
__global__ void finalize_kernel(const float* __restrict__ obj,
                                const float* __restrict__ reg,
                                const float* __restrict__ anc,
                                float* __restrict__ out) {
    int t = blockIdx.x * blockDim.x + threadIdx.x;
    if (t >= TOP_K) return;
    unsigned long long key = g_keys[t];
    if (key == 0ULL) {
        out[t * 4 + 0] = 0.f; out[t * 4 + 1] = 0.f; out[t * 4 + 2] = 0.f; out[t * 4 + 3] = 0.f;
        out[TOP_K * 4 + t * 2 + 0] = 0.f; out[TOP_K * 4 + t * 2 + 1] = 0.f;
        g_x1[t] = 0.f; g_y1[t] = 0.f; g_x2[t] = 0.f; g_y2[t] = 0.f; g_area[t] = 0.f;
        return;
    }
    unsigned idx = 0xFFFFFFFFu - (unsigned)(key & 0xFFFFFFFFull);

    const float* po = obj + (size_t)idx * 2;
    float p0;
    float p1 = softmax_p1(po[0], po[1], p0);

    const float* pr = reg + (size_t)idx * 4;
    float r0 = pr[0], r1 = pr[1], r2 = pr[2], r3 = pr[3];
    const float* pa = anc + (size_t)idx * 4;
    float a0 = pa[0], a1 = pa[1], a2 = pa[2], a3 = pa[3];

    float cx = __fadd_rn(__fadd_rn(a0, __fmul_rn(a2, 0.5f)), __fmul_rn(r0, a2));
    float cy = __fadd_rn(__fadd_rn(a1, __fmul_rn(a3, 0.5f)), __fmul_rn(r1, a3));
    float w  = __fmul_rn(a2, expf(r2));
    float h  = __fmul_rn(a3, expf(r3));
    float x1u = __fsub_rn(cx, __fmul_rn(w, 0.5f));
    float y1u = __fsub_rn(cy, __fmul_rn(h, 0.5f));

    float x1 = fminf(fmaxf(x1u, 0.0f), IMG_DIM);
    float y1 = fminf(fmaxf(y1u, 0.0f), IMG_DIM);
    float x2 = fminf(fmaxf(__fadd_rn(x1u, w), 0.0f), IMG_DIM);
    float y2 = fminf(fmaxf(__fadd_rn(y1u, h), 0.0f), IMG_DIM);
    float bw = __fsub_rn(x2, x1);
    float bh = __fsub_rn(y2, y1);

    out[t * 4 + 0] = x1;
    out[t * 4 + 1] = y1;
    out[t * 4 + 2] = bw;
    out[t * 4 + 3] = bh;
    out[TOP_K * 4 + t * 2 + 0] = p0;
    out[TOP_K * 4 + t * 2 + 1] = p1;

    g_x1[t] = x1;
    g_y1[t] = y1;
    g_x2[t] = __fadd_rn(x1, bw);
    g_y2[t] = __fadd_rn(y1, bh);
    g_area[t] = __fmul_rn(bw, bh);
}

// ---------------- K6: NMS bitmask (upper triangle) + compact diagonal ----------
__global__ void mask_kernel() {
    int cb = blockIdx.x, rb = blockIdx.y;
    if (cb < rb) return;
    int tid = threadIdx.x;
    __shared__ float sx1[64], sy1[64], sx2[64], sy2[64], sa[64];
    int j0 = cb * 64 + tid;
    if (j0 < TOP_K) {
        sx1[tid] = g_x1[j0]; sy1[tid] = g_y1[j0];
        sx2[tid] = g_x2[j0]; sy2[tid] = g_y2[j0];
        sa[tid]  = g_area[j0];
    }
    __syncthreads();
    int i = rb * 64 + tid;
    if (i >= TOP_K) return;
    float x1i = g_x1[i], y1i = g_y1[i], x2i = g_x2[i], y2i = g_y2[i], ai = g_area[i];
    unsigned long long bits = 0ULL;
    int jmax = min(64, TOP_K - cb * 64);
    for (int jj = 0; jj < jmax; jj++) {
        int j = cb * 64 + jj;
        if (j > i) {
            float xx1 = fmaxf(x1i, sx1[jj]);
            float yy1 = fmaxf(y1i, sy1[jj]);
            float xx2 = fminf(x2i, sx2[jj]);
            float yy2 = fminf(y2i, sy2[jj]);
            float iw = fmaxf(__fsub_rn(xx2, xx1), 0.0f);
            float ih = fmaxf(__fsub_rn(yy2, yy1), 0.0f);
            float inter = __fmul_rn(iw, ih);
            float denom = __fadd_rn(__fsub_rn(__fadd_rn(ai, sa[jj]), inter), 1e-8f);
            float iou = __fdiv_rn(inter, denom);
            if (iou > NMS_IOU_T) bits |= (1ULL << jj);
        }
    }
    g_mask[(size_t)i * ROW_WORDS + cb] = bits;
    if (rb == cb) g_diag[cb * 64 + tid] = bits;     // coalesced copy for reduce
}

// ---------------- K7: blocked greedy reduce, 64 threads ------------------------
// Thread t (t < 63) owns removed-column word t in a register. Per group g:
// thread g publishes its column; thread 0 resolves 64 bits serially on a
// register-resident diagonal; keepm broadcast; all column owners OR kept rows
// in parallel (fully unrolled predicated loads -> high MLP, coalesced rows).
__global__ void __launch_bounds__(64) nms_reduce_kernel(float* __restrict__ keep_out) {
    const int tid = threadIdx.x;
    __shared__ unsigned long long s_word;
    __shared__ unsigned long long s_keep;

    unsigned long long acc = 0ULL;     // column word owned by this thread
    unsigned long long diag[64];       // thread 0 only (literal-indexed -> regs)

    if (tid == 0) {
        #pragma unroll
        for (int q = 0; q < 64; q++) diag[q] = g_diag[q];
        s_word = 0ULL;
    }
    __syncthreads();

    for (int g = 0; g < N_GROUPS; g++) {
        const int r0 = g * 64;

        // Publish current removed-word for this group (acc is current: all
        // boundaries from groups < g were applied in earlier iterations).
        if (tid == g && g > 0) s_word = acc;
        __syncthreads();

        // Serial greedy resolve on thread 0 (sign-extend + LOP3 chain).
        if (tid == 0) {
            unsigned long long word = s_word;
            unsigned long long keepm = 0ULL;
            #pragma unroll
            for (int jj = 0; jj < 64; jj++) {
                unsigned long long rem =
                    (unsigned long long)(((long long)(word << (63 - jj))) >> 63);
                word |= diag[jj] & ~rem;
                keepm |= ~rem & (1ULL << jj);
            }
            s_keep = keepm;
        }
        __syncthreads();
        const unsigned long long keepm = s_keep;

        // keep output: one row per thread.
        int r = r0 + tid;
        if (r < TOP_K) keep_out[r] = (float)((keepm >> tid) & 1ULL);

        // Prefetch next diagonal (thread 0, off-chain, overlaps boundary).
        if (tid == 0 && g + 1 < N_GROUPS) {
            #pragma unroll
            for (int q = 0; q < 64; q++) diag[q] = g_diag[(g + 1) * 64 + q];
        }

        // Boundary: OR kept rows' column word into acc (coalesced across threads).
        if (tid < COL_BLOCKS) {
            const unsigned long long* base = g_mask + (size_t)r0 * ROW_WORDS + tid;
            #pragma unroll
            for (int jj = 0; jj < 64; jj++) {
                unsigned long long m = 0ULL - ((keepm >> jj) & 1ULL);  // kept -> ones
                acc |= base[(size_t)jj * ROW_WORDS] & m;
            }
        }
        __syncthreads();
    }
}

// ---------------- launch -------------------------------------------------------
extern "C" void kernel_launch(void* const* d_in, const int* in_sizes, int n_in,
                              void* d_out, int out_size) {
    const float* obj = (const float*)d_in[0];
    const float* reg = (const float*)d_in[1];
    const float* anc = (const float*)d_in[2];
    float* out = (float*)d_out;

    zero_kernel<<<N_BINS / 256, 256>>>();
    hist_kernel<<<(N_ANCH + 255) / 256, 256>>>(obj);
    bsum_kernel<<<1024, 1024>>>();
    cut_kernel<<<1, 1024>>>();
    collect_kernel<<<(N_ANCH + 255) / 256, 256>>>(obj);
    sort_kernel<<<1, 1024>>>();
    finalize_kernel<<<(TOP_K + 255) / 256, 256>>>(obj, reg, anc, out);
    mask_kernel<<<dim3(COL_BLOCKS, COL_BLOCKS), 64>>>();
    nms_reduce_kernel<<<1, 64>>>(out + TOP_K * 4 + TOP_K * 2);
}

// round 6
// speedup vs baseline: 6.4971x; 2.0092x over previous
#include <cuda_runtime.h>
#include <cstdint>

#define H_FEAT 512
#define W_FEAT 512
#define K_ANCH 9
#define N_ANCH (H_FEAT * W_FEAT * K_ANCH)   // 2359296
#define TOP_K 4000
#define IMG_DIM 16384.0f
#define NMS_IOU_T 0.3f
#define N_BINS (1 << 20)
#define BIN_SHIFT 12
#define CAP 4096
#define COL_BLOCKS 63
#define ROW_WORDS 64                         // padded row stride (512B)
#define MASK_ROWS 4096
#define N_GROUPS 63

// ---------------- static device scratch (no allocation allowed) ----------------
__device__ unsigned int        g_hist[N_BINS];            // 4 MB
__device__ unsigned int        g_bsum[1024];
__device__ unsigned int        g_count;
__device__ unsigned int        g_cutlow;
__device__ unsigned long long  g_keys[CAP];
__device__ float               g_x1[TOP_K], g_y1[TOP_K], g_x2[TOP_K], g_y2[TOP_K], g_area[TOP_K];
// Zero-initialized at load. Lower-triangle/padding words NEVER written -> stay 0.
__device__ unsigned long long  g_mask[(size_t)MASK_ROWS * ROW_WORDS];   // 2 MB
__device__ __align__(16) unsigned long long g_diag[4096];               // 63*64 used

// ---------------- helpers (forbid FMA contraction / fast-math drift) ----------
__device__ __forceinline__ float softmax_p1(float l0, float l1, float& p0) {
    float m  = fmaxf(l0, l1);
    float e0 = expf(__fsub_rn(l0, m));
    float e1 = expf(__fsub_rn(l1, m));
    float s  = __fadd_rn(e0, e1);
    p0 = __fdiv_rn(e0, s);
    return __fdiv_rn(e1, s);
}

// warp-inclusive suffix sum (lane l gets sum of lanes >= l)
__device__ __forceinline__ unsigned warp_suffix(unsigned v) {
    #pragma unroll
    for (int off = 1; off < 32; off <<= 1) {
        unsigned u = __shfl_down_sync(0xffffffffu, v, off);
        if ((threadIdx.x & 31) + off < 32) v += u;
    }
    return v;
}

// ---------------- K0: reset ----------------------------------------------------
__global__ void zero_kernel() {   // 1024 x 256, uint4 stores
    int i = blockIdx.x * blockDim.x + threadIdx.x;
    reinterpret_cast<uint4*>(g_hist)[i] = make_uint4(0u, 0u, 0u, 0u);
    if (i == 0) g_count = 0u;
}

// ---------------- K1: histogram of d = l1 - l0 bits (no exp/div) ---------------
__global__ void hist_kernel(const float* __restrict__ obj) {
    int i = blockIdx.x * blockDim.x + threadIdx.x;   // pair of anchors
    if (i >= N_ANCH / 2) return;
    float4 v = reinterpret_cast<const float4*>(obj)[i];
    float d0 = __fsub_rn(v.y, v.x);
    float d1 = __fsub_rn(v.w, v.z);
    if (d0 > 0.0f) atomicAdd(&g_hist[__float_as_uint(d0) >> BIN_SHIFT], 1u);
    if (d1 > 0.0f) atomicAdd(&g_hist[__float_as_uint(d1) >> BIN_SHIFT], 1u);
}

// ---------------- K2a: coarse per-1024-bin sums --------------------------------
__global__ void bsum_kernel() {   // 1024 x 256
    __shared__ unsigned sw[8];
    int t = threadIdx.x;
    uint4 a = reinterpret_cast<const uint4*>(g_hist + blockIdx.x * 1024)[t];
    unsigned v = a.x + a.y + a.z + a.w;
    #pragma unroll
    for (int off = 16; off > 0; off >>= 1) v += __shfl_down_sync(0xffffffffu, v, off);
    if ((t & 31) == 0) sw[t >> 5] = v;
    __syncthreads();
    if (t == 0) {
        unsigned s = 0;
        #pragma unroll
        for (int q = 0; q < 8; q++) s += sw[q];
        g_bsum[blockIdx.x] = s;
    }
}

// ---------------- K2b: two-level suffix scan -> g_cutlow -----------------------
__global__ void cut_kernel() {
    __shared__ unsigned s_warp[32];
    __shared__ unsigned s_above[32];
    __shared__ unsigned suf[1025];
    __shared__ int s_cb;
    __shared__ unsigned s_abv;
    int t = threadIdx.x, lane = t & 31, w = t >> 5;
    if (t == 0) s_cb = -1;

    // phase 1: coarse suffix scan over g_bsum
    unsigned v = warp_suffix(g_bsum[t]);
    if (lane == 0) s_warp[w] = v;
    __syncthreads();
    if (w == 0) {
        unsigned u = warp_suffix(s_warp[lane]);
        unsigned ab = __shfl_down_sync(0xffffffffu, u, 1);
        s_above[lane] = (lane < 31) ? ab : 0u;
    }
    __syncthreads();
    suf[t] = v + s_above[w];
    if (t == 0) suf[1024] = 0u;
    __syncthreads();
    if (suf[t] >= (unsigned)TOP_K && suf[t + 1] < (unsigned)TOP_K) {
        s_cb = t; s_abv = suf[t + 1];
    }
    __syncthreads();
    int cb = s_cb;
    if (cb < 0) { if (t == 0) g_cutlow = 0u; return; }
    unsigned above = s_abv;
    __syncthreads();

    // phase 2: fine suffix scan within coarse block cb
    v = warp_suffix(g_hist[cb * 1024 + t]);
    if (lane == 0) s_warp[w] = v;
    __syncthreads();
    if (w == 0) {
        unsigned u = warp_suffix(s_warp[lane]);
        unsigned ab = __shfl_down_sync(0xffffffffu, u, 1);
        s_above[lane] = (lane < 31) ? ab : 0u;
    }
    __syncthreads();
    suf[t] = v + s_above[w] + above;
    if (t == 0) suf[1024] = above;
    __syncthreads();
    if (suf[t] >= (unsigned)TOP_K && suf[t + 1] < (unsigned)TOP_K) {
        int cutbin = cb * 1024 + t;
        g_cutlow = (cutbin > 0) ? (unsigned)(cutbin - 1) : 0u;  // -1 bin slack
    }
}

// ---------------- K3: collect candidates, exact p1 keys ------------------------
__global__ void collect_kernel(const float* __restrict__ obj) {
    int i = blockIdx.x * blockDim.x + threadIdx.x;   // pair of anchors
    if (i >= N_ANCH / 2) return;
    float4 v = reinterpret_cast<const float4*>(obj)[i];
    unsigned cut = g_cutlow;
    #pragma unroll
    for (int h = 0; h < 2; h++) {
        float l0 = h ? v.z : v.x;
        float l1 = h ? v.w : v.y;
        float d = __fsub_rn(l1, l0);
        if (d > 0.0f && (__float_as_uint(d) >> BIN_SHIFT) >= cut) {
            // exact p1, bit-identical to full softmax for d > 0 (e1 = expf(0) = 1)
            float e0 = expf(__fsub_rn(l0, l1));
            float s  = __fadd_rn(e0, 1.0f);
            float p1 = __fdiv_rn(1.0f, s);
            unsigned idx = 2u * (unsigned)i + (unsigned)h;
            unsigned pos = atomicAdd(&g_count, 1u);
            if (pos < CAP) {
                g_keys[pos] = ((unsigned long long)__float_as_uint(p1) << 32) |
                              (unsigned long long)(0xFFFFFFFFu - idx);
            }
        }
    }
}

// ---------------- K4: one-block bitonic sort (descending), n = 4096 ------------
__global__ void sort_kernel() {
    __shared__ unsigned long long s[CAP];
    unsigned cnt = g_count;
    if (cnt > CAP) cnt = CAP;
    for (int i = threadIdx.x; i < CAP; i += blockDim.x)
        s[i] = (i < (int)cnt) ? g_keys[i] : 0ULL;
    __syncthreads();
    for (int k = 2; k <= CAP; k <<= 1) {
        for (int j = k >> 1; j > 0; j >>= 1) {
            for (int i = threadIdx.x; i < CAP; i += blockDim.x) {
                int ixj = i ^ j;
                if (ixj > i) {
                    unsigned long long a = s[i], b = s[ixj];
                    bool up = ((i & k) == 0);
                    if (up ? (a < b) : (a > b)) { s[i] = b; s[ixj] = a; }
                }
            }
            __syncthreads();
        }
    }
    for (int i = threadIdx.x; i < CAP; i += blockDim.x) g_keys[i] = s[i];
}

// ---------------- K5: decode boxes, write b & o, prep NMS inputs ---------------
__global__ void finalize_kernel(const float* __restrict__ obj,
                                const float* __restrict__ reg,
                                const float* __restrict__ anc,
                                float* __restrict__ out) {
    int t = blockIdx.x * blockDim.x + threadIdx.x;
    if (t >= TOP_K) return;
    unsigned long long key = g_keys[t];
    if (key == 0ULL) {
        out[t * 4 + 0] = 0.f; out[t * 4 + 1] = 0.f; out[t * 4 + 2] = 0.f; out[t * 4 + 3] = 0.f;
        out[TOP_K * 4 + t * 2 + 0] = 0.f; out[TOP_K * 4 + t * 2 + 1] = 0.f;
        g_x1[t] = 0.f; g_y1[t] = 0.f; g_x2[t] = 0.f; g_y2[t] = 0.f; g_area[t] = 0.f;
        return;
    }
    unsigned idx = 0xFFFFFFFFu - (unsigned)(key & 0xFFFFFFFFull);

    const float* po = obj + (size_t)idx * 2;
    float p0;
    float p1 = softmax_p1(po[0], po[1], p0);

    const float* pr = reg + (size_t)idx * 4;
    float r0 = pr[0], r1 = pr[1], r2 = pr[2], r3 = pr[3];
    const float* pa = anc + (size_t)idx * 4;
    float a0 = pa[0], a1 = pa[1], a2 = pa[2], a3 = pa[3];

    float cx = __fadd_rn(__fadd_rn(a0, __fmul_rn(a2, 0.5f)), __fmul_rn(r0, a2));
    float cy = __fadd_rn(__fadd_rn(a1, __fmul_rn(a3, 0.5f)), __fmul_rn(r1, a3));
    float w  = __fmul_rn(a2, expf(r2));
    float h  = __fmul_rn(a3, expf(r3));
    float x1u = __fsub_rn(cx, __fmul_rn(w, 0.5f));
    float y1u = __fsub_rn(cy, __fmul_rn(h, 0.5f));

    float x1 = fminf(fmaxf(x1u, 0.0f), IMG_DIM);
    float y1 = fminf(fmaxf(y1u, 0.0f), IMG_DIM);
    float x2 = fminf(fmaxf(__fadd_rn(x1u, w), 0.0f), IMG_DIM);
    float y2 = fminf(fmaxf(__fadd_rn(y1u, h), 0.0f), IMG_DIM);
    float bw = __fsub_rn(x2, x1);
    float bh = __fsub_rn(y2, y1);

    out[t * 4 + 0] = x1;
    out[t * 4 + 1] = y1;
    out[t * 4 + 2] = bw;
    out[t * 4 + 3] = bh;
    out[TOP_K * 4 + t * 2 + 0] = p0;
    out[TOP_K * 4 + t * 2 + 1] = p1;

    g_x1[t] = x1;
    g_y1[t] = y1;
    g_x2[t] = __fadd_rn(x1, bw);
    g_y2[t] = __fadd_rn(y1, bh);
    g_area[t] = __fmul_rn(bw, bh);
}

// ---------------- K6: NMS bitmask (upper triangle) + compact diagonal ----------
__global__ void mask_kernel() {
    int cb = blockIdx.x, rb = blockIdx.y;
    if (cb < rb) return;
    int tid = threadIdx.x;
    __shared__ float sx1[64], sy1[64], sx2[64], sy2[64], sa[64];
    int j0 = cb * 64 + tid;
    if (j0 < TOP_K) {
        sx1[tid] = g_x1[j0]; sy1[tid] = g_y1[j0];
        sx2[tid] = g_x2[j0]; sy2[tid] = g_y2[j0];
        sa[tid]  = g_area[j0];
    }
    __syncthreads();
    int i = rb * 64 + tid;
    if (i >= TOP_K) return;
    float x1i = g_x1[i], y1i = g_y1[i], x2i = g_x2[i], y2i = g_y2[i], ai = g_area[i];
    unsigned long long bits = 0ULL;
    int jmax = min(64, TOP_K - cb * 64);
    for (int jj = 0; jj < jmax; jj++) {
        int j = cb * 64 + jj;
        if (j > i) {
            float xx1 = fmaxf(x1i, sx1[jj]);
            float yy1 = fmaxf(y1i, sy1[jj]);
            float xx2 = fminf(x2i, sx2[jj]);
            float yy2 = fminf(y2i, sy2[jj]);
            float iw = fmaxf(__fsub_rn(xx2, xx1), 0.0f);
            float ih = fmaxf(__fsub_rn(yy2, yy1), 0.0f);
            float inter = __fmul_rn(iw, ih);
            float denom = __fadd_rn(__fsub_rn(__fadd_rn(ai, sa[jj]), inter), 1e-8f);
            float iou = __fdiv_rn(inter, denom);
            if (iou > NMS_IOU_T) bits |= (1ULL << jj);
        }
    }
    g_mask[(size_t)i * ROW_WORDS + cb] = bits;
    if (rb == cb) g_diag[cb * 64 + tid] = bits;     // coalesced copy for reduce
}

// ---------------- K7: pipelined blocked greedy reduce, 256 threads -------------
// Thread (c, p) (c = tid&63 column, p = tid>>6 row-slice) holds 16 boundary
// words per group, double-buffered so loads for group g+1 issue during the
// serial resolve of group g. Diagonal blocks double-buffered in smem, fetched
// by p==1 threads. Resolve chain: SHF+SHF+LOP3 = ~12 cyc/bit on thread 0.
__global__ void __launch_bounds__(256) nms_reduce_kernel(float* __restrict__ keep_out) {
    const int tid = threadIdx.x;
    const int c = tid & 63;
    const int p = tid >> 6;
    __shared__ unsigned long long s_diag[2][64];
    __shared__ unsigned long long s_part[4];
    __shared__ unsigned long long s_keep;

    unsigned long long acc = 0ULL;
    unsigned long long rcur[16], rnxt[16];

    // prologue: diag(0) and boundary rows of group 0
    if (tid < 64) s_diag[0][tid] = g_diag[tid];
    {
        const unsigned long long* base = g_mask + (size_t)(p * 16) * ROW_WORDS + c;
        #pragma unroll
        for (int jj = 0; jj < 16; jj++) rcur[jj] = base[(size_t)jj * ROW_WORDS];
    }
    __syncthreads();

    for (int g = 0; g < N_GROUPS; g++) {
        const int buf = g & 1;

        // publish partial removed-words for this group's column
        if (c == g) s_part[p] = acc;
        __syncthreads();

        // serial greedy resolve on thread 0 (diag reads are off-chain LDS)
        if (tid == 0) {
            unsigned long long word = s_part[0] | s_part[1] | s_part[2] | s_part[3];
            unsigned long long keepm = 0ULL;
            #pragma unroll
            for (int jj = 0; jj < 64; jj++) {
                unsigned long long sext =
                    (unsigned long long)(((long long)(word << (63 - jj))) >> 63);
                word  |= s_diag[buf][jj] & ~sext;
                keepm |= ~sext & (1ULL << jj);
            }
            s_keep = keepm;
        }

        // prefetch next diagonal (idle p==1 threads) and next boundary rows
        if (g + 1 < N_GROUPS) {
            if (p == 1) s_diag[buf ^ 1][c] = g_diag[(g + 1) * 64 + c];
            const unsigned long long* base =
                g_mask + (size_t)((g + 1) * 64 + p * 16) * ROW_WORDS + c;
            #pragma unroll
            for (int jj = 0; jj < 16; jj++) rnxt[jj] = base[(size_t)jj * ROW_WORDS];
        }
        __syncthreads();
        const unsigned long long keepm = s_keep;

        // keep output (64 rows, one per thread of slice p==0..)
        if (tid < 64) {
            int r = g * 64 + tid;
            if (r < TOP_K) keep_out[r] = (float)((keepm >> tid) & 1ULL);
        }

        // boundary OR: kept rows' words into this thread's column accumulator
        #pragma unroll
        for (int jj = 0; jj < 16; jj++) {
            unsigned long long m = 0ULL - ((keepm >> (p * 16 + jj)) & 1ULL);
            acc |= rcur[jj] & m;
        }
        #pragma unroll
        for (int jj = 0; jj < 16; jj++) rcur[jj] = rnxt[jj];
    }
}

// ---------------- launch -------------------------------------------------------
extern "C" void kernel_launch(void* const* d_in, const int* in_sizes, int n_in,
                              void* d_out, int out_size) {
    const float* obj = (const float*)d_in[0];
    const float* reg = (const float*)d_in[1];
    const float* anc = (const float*)d_in[2];
    float* out = (float*)d_out;

    zero_kernel<<<1024, 256>>>();
    hist_kernel<<<(N_ANCH / 2 + 255) / 256, 256>>>(obj);
    bsum_kernel<<<1024, 256>>>();
    cut_kernel<<<1, 1024>>>();
    collect_kernel<<<(N_ANCH / 2 + 255) / 256, 256>>>(obj);
    sort_kernel<<<1, 1024>>>();
    finalize_kernel<<<(TOP_K + 255) / 256, 256>>>(obj, reg, anc, out);
    mask_kernel<<<dim3(COL_BLOCKS, COL_BLOCKS), 64>>>();
    nms_reduce_kernel<<<1, 256>>>(out + TOP_K * 4 + TOP_K * 2);
}